// round 11
// baseline (speedup 1.0000x reference)
#include <cuda_runtime.h>
#include <cuda_bf16.h>
#include <cstdint>

#define D_MODEL 1024
#define N_HEADS 16
#define DKH     64
#define B_      4
#define T_      2048
#define M_TOT   (B_ * T_)        // 8192
#define N_QKV   (3 * D_MODEL)    // 3072
#define GK      1024

// ---------------- scratch (device globals; no allocation allowed) ----------
// Q/K: pair-interleaved {hi(bf16x2), lo(bf16x2)} per dk-pair. Q pre-scaled.
__device__ uint2 g_qp[(size_t)64 * T_ * 32];               // 32 MB
__device__ uint2 g_kp[(size_t)64 * T_ * 32];               // 32 MB
__device__ __nv_bfloat16 g_vh[(size_t)64 * DKH * T_];      // 16 MB  V^T [dk][t]
__device__ __nv_bfloat16 g_vl[(size_t)64 * DKH * T_];      // 16 MB
__device__ float g_attn[(size_t)M_TOT * D_MODEL];          // 32 MB

// ============================ helpers ======================================
#define MMA_BF16(D, A, b0, b1) \
    asm volatile("mma.sync.aligned.m16n8k16.row.col.f32.bf16.bf16.f32 " \
        "{%0,%1,%2,%3}, {%4,%5,%6,%7}, {%8,%9}, {%0,%1,%2,%3};" \
        : "+f"((D)[0]), "+f"((D)[1]), "+f"((D)[2]), "+f"((D)[3]) \
        : "r"((A)[0]), "r"((A)[1]), "r"((A)[2]), "r"((A)[3]), "r"(b0), "r"(b1))

__device__ __forceinline__ void bf16_split(float x, unsigned short& h, unsigned short& l)
{
    __nv_bfloat16 hb = __float2bfloat16(x);
    h = __bfloat16_as_ushort(hb);
    l = __bfloat16_as_ushort(__float2bfloat16(x - __bfloat162float(hb)));
}
// pack (a at k, b at k+1) into hi/lo bf16x2 regs (low half = a)
__device__ __forceinline__ void split2(float a, float b, uint32_t& hi, uint32_t& lo)
{
    unsigned short ha, la, hb, lb;
    bf16_split(a, ha, la);
    bf16_split(b, hb, lb);
    hi = (uint32_t)ha | ((uint32_t)hb << 16);
    lo = (uint32_t)la | ((uint32_t)lb << 16);
}

// ===================== double-buffered bf16 HMMA GEMM ======================
// C[M,N] = A[M,K](fp32) @ B[K,N](fp32):  C = AhBh + AhBl + AlBh
// CTA 128x128, 8 warps (2x4), warp 64x32, BK=16, 2-stage, pair-interleaved smem.
#define BKS  16
#define NST  (GK / BKS)
#define SAP  12     // sA row stride in uint2 pairs (8 data + 4 pad)
#define SBP  10     // sB row stride in uint2 pairs

template<int MODE>
__global__ __launch_bounds__(256)
void gemm_mma(const float* __restrict__ Ap, const float* __restrict__ Bp,
              float* __restrict__ Cp, int N)
{
    __shared__ uint2 sA[2][128][SAP];   // [buf][m][kpair] {hi2, lo2}  24.0 KB
    __shared__ uint2 sB[2][128][SBP];   // [buf][n][kpair]             20.0 KB

    const int tid  = threadIdx.x;
    const int wid  = tid >> 5;
    const int lane = tid & 31;
    const int wm   = wid & 1;
    const int wn   = wid >> 1;
    const int gid  = lane >> 2;
    const int tig  = lane & 3;
    const int row0 = blockIdx.y * 128;
    const int col0 = blockIdx.x * 128;

    const float* A = (MODE == 1) ? g_attn : Ap;

    float d[4][4][4];
    #pragma unroll
    for (int i = 0; i < 4; i++)
        #pragma unroll
        for (int j = 0; j < 4; j++)
            #pragma unroll
            for (int e = 0; e < 4; e++) d[i][j][e] = 0.f;

    // A loads: thread -> rows ar0, ar0+64; elems 4*apq..4*apq+3 (pairs 2apq, 2apq+1)
    const int ar0 = tid >> 2, apq = tid & 3;
    // B loads: warp = kpair (k = 2*wid, 2*wid+1); lane covers n = lane + 32c
    float4 va[2];
    float  vb0[4], vb1[4];

    // ---- prologue: load stage 0 ----
    #pragma unroll
    for (int i = 0; i < 2; i++)
        va[i] = *(const float4*)(A + (size_t)(row0 + ar0 + i * 64) * GK + 4 * apq);
    #pragma unroll
    for (int c = 0; c < 4; c++) {
        vb0[c] = Bp[(size_t)(2 * wid) * N + col0 + lane + 32 * c];
        vb1[c] = Bp[(size_t)(2 * wid + 1) * N + col0 + lane + 32 * c];
    }
    #pragma unroll
    for (int i = 0; i < 2; i++) {
        const int ra = ar0 + i * 64;
        uint32_t h0, l0, h1, l1;
        split2(va[i].x, va[i].y, h0, l0);
        split2(va[i].z, va[i].w, h1, l1);
        sA[0][ra][2 * apq]     = make_uint2(h0, l0);
        sA[0][ra][2 * apq + 1] = make_uint2(h1, l1);
    }
    #pragma unroll
    for (int c = 0; c < 4; c++) {
        uint32_t h, l;
        split2(vb0[c], vb1[c], h, l);
        sB[0][lane + 32 * c][wid] = make_uint2(h, l);
    }
    __syncthreads();

    for (int kt = 0; kt < NST; kt++) {
        const int buf = kt & 1;
        // ---- prefetch stage kt+1 ----
        if (kt + 1 < NST) {
            const int k0 = (kt + 1) * BKS;
            #pragma unroll
            for (int i = 0; i < 2; i++)
                va[i] = *(const float4*)(A + (size_t)(row0 + ar0 + i * 64) * GK + k0 + 4 * apq);
            #pragma unroll
            for (int c = 0; c < 4; c++) {
                vb0[c] = Bp[(size_t)(k0 + 2 * wid) * N + col0 + lane + 32 * c];
                vb1[c] = Bp[(size_t)(k0 + 2 * wid + 1) * N + col0 + lane + 32 * c];
            }
        }

        // ---- compute stage kt (frag loads are LDS.64, hi+lo together) ----
        uint32_t Ah[4][4], Al[4][4];
        #pragma unroll
        for (int mi = 0; mi < 4; mi++) {
            const int r0 = wm * 64 + mi * 16 + gid;
            uint2 a0 = sA[buf][r0][tig];
            uint2 a1 = sA[buf][r0 + 8][tig];
            uint2 a2 = sA[buf][r0][tig + 4];
            uint2 a3 = sA[buf][r0 + 8][tig + 4];
            Ah[mi][0] = a0.x; Ah[mi][1] = a1.x; Ah[mi][2] = a2.x; Ah[mi][3] = a3.x;
            Al[mi][0] = a0.y; Al[mi][1] = a1.y; Al[mi][2] = a2.y; Al[mi][3] = a3.y;
        }
        #pragma unroll
        for (int ng = 0; ng < 4; ng++) {
            const int nr = wn * 32 + ng * 8 + gid;
            uint2 b0 = sB[buf][nr][tig];
            uint2 b1 = sB[buf][nr][tig + 4];
            #pragma unroll
            for (int mi = 0; mi < 4; mi++) {
                MMA_BF16(d[mi][ng], Ah[mi], b0.x, b1.x);
                MMA_BF16(d[mi][ng], Ah[mi], b0.y, b1.y);
                MMA_BF16(d[mi][ng], Al[mi], b0.x, b1.x);
            }
        }

        // ---- store stage kt+1 ----
        if (kt + 1 < NST) {
            const int nb = buf ^ 1;
            #pragma unroll
            for (int i = 0; i < 2; i++) {
                const int ra = ar0 + i * 64;
                uint32_t h0, l0, h1, l1;
                split2(va[i].x, va[i].y, h0, l0);
                split2(va[i].z, va[i].w, h1, l1);
                sA[nb][ra][2 * apq]     = make_uint2(h0, l0);
                sA[nb][ra][2 * apq + 1] = make_uint2(h1, l1);
            }
            #pragma unroll
            for (int c = 0; c < 4; c++) {
                uint32_t h, l;
                split2(vb0[c], vb1[c], h, l);
                sB[nb][lane + 32 * c][wid] = make_uint2(h, l);
            }
        }
        __syncthreads();
    }

    // ---------------- epilogue ----------------
    #pragma unroll
    for (int mi = 0; mi < 4; mi++)
        #pragma unroll
        for (int ng = 0; ng < 4; ng++) {
            const int n = col0 + wn * 32 + ng * 8 + tig * 2;
            #pragma unroll
            for (int h = 0; h < 2; h++) {
                const int m = row0 + wm * 64 + mi * 16 + gid + h * 8;
                float2 v;
                v.x = d[mi][ng][h * 2 + 0];
                v.y = d[mi][ng][h * 2 + 1];
                if (MODE == 0) {
                    const int b = m >> 11, t = m & (T_ - 1);
                    const int sidx = n >> 10;
                    const int dmi  = n & (D_MODEL - 1);
                    const int hh = dmi >> 6, dk = dmi & (DKH - 1);
                    const int bh = (b << 4) + hh;
                    if (sidx == 0) {            // Q: pre-scale + split, interleaved
                        uint32_t hi, lo;
                        split2(0.125f * v.x, 0.125f * v.y, hi, lo);
                        g_qp[((size_t)bh * T_ + t) * 32 + (dk >> 1)] = make_uint2(hi, lo);
                    } else if (sidx == 1) {     // K: split, interleaved
                        uint32_t hi, lo;
                        split2(v.x, v.y, hi, lo);
                        g_kp[((size_t)bh * T_ + t) * 32 + (dk >> 1)] = make_uint2(hi, lo);
                    } else {                    // V: split + transpose to [dk][t]
                        unsigned short h0, l0, h1, l1;
                        bf16_split(v.x, h0, l0);
                        bf16_split(v.y, h1, l1);
                        const size_t i0 = ((size_t)bh * DKH + dk) * T_ + t;
                        g_vh[i0] = __ushort_as_bfloat16(h0);
                        g_vl[i0] = __ushort_as_bfloat16(l0);
                        g_vh[i0 + T_] = __ushort_as_bfloat16(h1);
                        g_vl[i0 + T_] = __ushort_as_bfloat16(l1);
                    }
                } else {
                    *(float2*)(Cp + (size_t)m * N + n) = v;
                }
            }
        }
}

// ===================== bf16 HMMA causal flash attention ====================
// 128 q-rows/CTA, 8 warps x 16 rows, 64-key tiles. Pair-interleaved smem:
// sK/sV[row][pair] = {hi(k,k+1), lo(k,k+1)}; frag loads are single LDS.64.
#define SPR 36   // row stride in uint2 pairs (32 data + 4 pad) -> 288 B

__global__ __launch_bounds__(256, 2)
void attn_mma()
{
    __shared__ uint2 sK[64][SPR];   // 18 KB
    __shared__ uint2 sV[64][SPR];   // 18 KB

    const int bh  = blockIdx.y;
    const int q0  = blockIdx.x * 128;
    const int tid = threadIdx.x;
    const int wid = tid >> 5;
    const int lane = tid & 31;
    const int gid = lane >> 2;
    const int tig = lane & 3;

    const uint2* Kp = g_kp + (size_t)bh * T_ * 32;
    const __nv_bfloat16* Vh_g = g_vh + (size_t)bh * DKH * T_;
    const __nv_bfloat16* Vl_g = g_vl + (size_t)bh * DKH * T_;
    const float LOG2E = 1.4426950408889634f;

    // ---- Q fragments (staged through sK in two 64-row passes) ----
    uint32_t Qh[4][4], Ql[4][4];
    #pragma unroll
    for (int pass = 0; pass < 2; pass++) {
        #pragma unroll
        for (int i = 0; i < 4; i++) {
            const int c = tid + i * 256;         // 0..1023 uint4 chunks
            const int rr = c >> 4, ch = c & 15;  // 16 chunks per 32-pair row
            *(uint4*)&sK[rr][ch * 2] =
                *(const uint4*)(g_qp + ((size_t)bh * T_ + q0 + pass * 64 + rr) * 32 + ch * 2);
        }
        __syncthreads();
        if ((wid >> 2) == pass) {
            const int rb = (wid & 3) * 16 + gid;
            #pragma unroll
            for (int ks = 0; ks < 4; ks++) {
                const int p = 8 * ks + tig;
                uint2 q0v = sK[rb][p];
                uint2 q1v = sK[rb + 8][p];
                uint2 q2v = sK[rb][p + 4];
                uint2 q3v = sK[rb + 8][p + 4];
                Qh[ks][0] = q0v.x; Qh[ks][1] = q1v.x; Qh[ks][2] = q2v.x; Qh[ks][3] = q3v.x;
                Ql[ks][0] = q0v.y; Ql[ks][1] = q1v.y; Ql[ks][2] = q2v.y; Ql[ks][3] = q3v.y;
            }
        }
        __syncthreads();
    }

    float O[8][4];
    #pragma unroll
    for (int i = 0; i < 8; i++)
        #pragma unroll
        for (int e = 0; e < 4; e++) O[i][e] = 0.f;
    float mr[2] = {-1e30f, -1e30f}, lr[2] = {0.f, 0.f};

    const int qA = q0 + wid * 16 + gid;
    const int ntiles = (q0 >> 6) + 2;

    for (int t = 0; t < ntiles; t++) {
        const int k0 = t * 64;
        // ---- global loads first (in flight across the barrier) ----
        uint4 kc[4], vhc[2], vlc[2];
        #pragma unroll
        for (int i = 0; i < 4; i++) {
            const int c = tid + i * 256;
            const int rr = c >> 4, ch = c & 15;
            kc[i] = *(const uint4*)(Kp + (size_t)(k0 + rr) * 32 + ch * 2);
        }
        #pragma unroll
        for (int i = 0; i < 2; i++) {
            const int c = tid + i * 256;          // 0..511
            const int dkr = c >> 3, tch = c & 7;  // dk row, 8-elem chunk along t
            vhc[i] = *(const uint4*)(Vh_g + (size_t)dkr * T_ + k0 + tch * 8);
            vlc[i] = *(const uint4*)(Vl_g + (size_t)dkr * T_ + k0 + tch * 8);
        }
        __syncthreads();   // prev tile's compute done
        #pragma unroll
        for (int i = 0; i < 4; i++) {
            const int c = tid + i * 256;
            const int rr = c >> 4, ch = c & 15;
            *(uint4*)&sK[rr][ch * 2] = kc[i];
        }
        #pragma unroll
        for (int i = 0; i < 2; i++) {
            const int c = tid + i * 256;
            const int dkr = c >> 3, tch = c & 7;
            sV[dkr][tch * 4 + 0] = make_uint2(vhc[i].x, vlc[i].x);
            sV[dkr][tch * 4 + 1] = make_uint2(vhc[i].y, vlc[i].y);
            sV[dkr][tch * 4 + 2] = make_uint2(vhc[i].z, vlc[i].z);
            sV[dkr][tch * 4 + 3] = make_uint2(vhc[i].w, vlc[i].w);
        }
        __syncthreads();

        if (k0 <= q0 + wid * 16 + 15) {
            // ---- S = (Q*scale) @ K^T ----
            float S[8][4];
            #pragma unroll
            for (int i = 0; i < 8; i++)
                #pragma unroll
                for (int e = 0; e < 4; e++) S[i][e] = 0.f;
            #pragma unroll
            for (int ks = 0; ks < 4; ks++) {
                const int p = 8 * ks + tig;
                #pragma unroll
                for (int ng = 0; ng < 8; ng++) {
                    const int nr = ng * 8 + gid;
                    uint2 k0v = sK[nr][p];
                    uint2 k1v = sK[nr][p + 4];
                    MMA_BF16(S[ng], Qh[ks], k0v.x, k1v.x);
                    MMA_BF16(S[ng], Qh[ks], k0v.y, k1v.y);
                    MMA_BF16(S[ng], Ql[ks], k0v.x, k1v.x);
                }
            }
            // ---- causal mask ----
            if (k0 + 63 > q0 + wid * 16) {
                #pragma unroll
                for (int ng = 0; ng < 8; ng++)
                    #pragma unroll
                    for (int e = 0; e < 4; e++) {
                        const int key = k0 + ng * 8 + tig * 2 + (e & 1);
                        const int q   = qA + (e >> 1) * 8;
                        if (key > q) S[ng][e] = -1e30f;
                    }
            }
            // ---- online softmax ----
            #pragma unroll
            for (int h = 0; h < 2; h++) {
                float mt = -1e30f;
                #pragma unroll
                for (int ng = 0; ng < 8; ng++)
                    mt = fmaxf(mt, fmaxf(S[ng][2 * h], S[ng][2 * h + 1]));
                mt = fmaxf(mt, __shfl_xor_sync(0xffffffff, mt, 1));
                mt = fmaxf(mt, __shfl_xor_sync(0xffffffff, mt, 2));
                const float mn = fmaxf(mr[h], mt);
                const float alpha = exp2f((mr[h] - mn) * LOG2E);
                float rs = 0.f;
                #pragma unroll
                for (int ng = 0; ng < 8; ng++) {
                    float p0 = exp2f((S[ng][2 * h] - mn) * LOG2E);
                    float p1 = exp2f((S[ng][2 * h + 1] - mn) * LOG2E);
                    S[ng][2 * h] = p0;
                    S[ng][2 * h + 1] = p1;
                    rs += p0 + p1;
                }
                rs += __shfl_xor_sync(0xffffffff, rs, 1);
                rs += __shfl_xor_sync(0xffffffff, rs, 2);
                lr[h] = lr[h] * alpha + rs;
                mr[h] = mn;
                #pragma unroll
                for (int ng = 0; ng < 8; ng++) {
                    O[ng][2 * h] *= alpha;
                    O[ng][2 * h + 1] *= alpha;
                }
            }
            // ---- O += P @ V ----
            #pragma unroll
            for (int ks = 0; ks < 4; ks++) {
                uint32_t Ph[4], Pl[4];
                split2(S[2 * ks][0],     S[2 * ks][1],     Ph[0], Pl[0]);
                split2(S[2 * ks][2],     S[2 * ks][3],     Ph[1], Pl[1]);
                split2(S[2 * ks + 1][0], S[2 * ks + 1][1], Ph[2], Pl[2]);
                split2(S[2 * ks + 1][2], S[2 * ks + 1][3], Ph[3], Pl[3]);
                const int p = 8 * ks + tig;
                #pragma unroll
                for (int ng = 0; ng < 8; ng++) {
                    const int nr = ng * 8 + gid;
                    uint2 v0 = sV[nr][p];
                    uint2 v1 = sV[nr][p + 4];
                    MMA_BF16(O[ng], Ph, v0.x, v1.x);
                    MMA_BF16(O[ng], Ph, v0.y, v1.y);
                    MMA_BF16(O[ng], Pl, v0.x, v1.x);
                }
            }
        }
    }

    // ---- epilogue: normalize + write (B,T,D) ----
    const int b = bh >> 4, h = bh & 15;
    #pragma unroll
    for (int hh = 0; hh < 2; hh++) {
        const float inv = 1.f / lr[hh];
        const int q = qA + hh * 8;
        float* og = g_attn + ((size_t)(b * T_ + q)) * D_MODEL + h * DKH;
        #pragma unroll
        for (int ng = 0; ng < 8; ng++) {
            float2 v;
            v.x = O[ng][2 * hh] * inv;
            v.y = O[ng][2 * hh + 1] * inv;
            *(float2*)(og + ng * 8 + tig * 2) = v;
        }
    }
}

// ---------------------------------------------------------------------------
extern "C" void kernel_launch(void* const* d_in, const int* in_sizes, int n_in,
                              void* d_out, int out_size)
{
    const float* x     = (const float*)d_in[0];
    const float* w_qkv = (const float*)d_in[1];
    const float* w_out = (const float*)d_in[2];
    float* out = (float*)d_out;

    gemm_mma<0><<<dim3(N_QKV / 128, M_TOT / 128), 256>>>(x, w_qkv, nullptr, N_QKV);
    attn_mma<<<dim3(T_ / 128, B_ * N_HEADS), 256>>>();
    gemm_mma<1><<<dim3(D_MODEL / 128, M_TOT / 128), 256>>>(nullptr, w_out, out, D_MODEL);
}

// round 12
// speedup vs baseline: 1.3055x; 1.3055x over previous
#include <cuda_runtime.h>
#include <cuda_bf16.h>
#include <cstdint>

#define D_MODEL 1024
#define N_HEADS 16
#define DKH     64
#define B_      4
#define T_      2048
#define M_TOT   (B_ * T_)        // 8192
#define N_QKV   (3 * D_MODEL)    // 3072
#define GK      1024

// ---------------- scratch (device globals; no allocation allowed) ----------
// Q/K: bf16 hi/lo, [bh][t][dk] (Q pre-scaled by 0.125). V: [bh][dk][t].
__device__ __nv_bfloat16 g_qh[(size_t)64 * T_ * DKH];
__device__ __nv_bfloat16 g_ql[(size_t)64 * T_ * DKH];
__device__ __nv_bfloat16 g_kh[(size_t)64 * T_ * DKH];
__device__ __nv_bfloat16 g_kl[(size_t)64 * T_ * DKH];
__device__ __nv_bfloat16 g_vh[(size_t)64 * DKH * T_];
__device__ __nv_bfloat16 g_vl[(size_t)64 * DKH * T_];
__device__ float g_attn[(size_t)M_TOT * D_MODEL];

// ============================ helpers ======================================
#define MMA_BF16(D, A, b0, b1) \
    asm volatile("mma.sync.aligned.m16n8k16.row.col.f32.bf16.bf16.f32 " \
        "{%0,%1,%2,%3}, {%4,%5,%6,%7}, {%8,%9}, {%0,%1,%2,%3};" \
        : "+f"((D)[0]), "+f"((D)[1]), "+f"((D)[2]), "+f"((D)[3]) \
        : "r"((A)[0]), "r"((A)[1]), "r"((A)[2]), "r"((A)[3]), "r"(b0), "r"(b1))

__device__ __forceinline__ void bf16_split(float x, unsigned short& h, unsigned short& l)
{
    __nv_bfloat16 hb = __float2bfloat16(x);
    h = __bfloat16_as_ushort(hb);
    l = __bfloat16_as_ushort(__float2bfloat16(x - __bfloat162float(hb)));
}
// pack (a at k, b at k+1) into hi/lo bf16x2 regs (low half = a)
__device__ __forceinline__ void split2(float a, float b, uint32_t& hi, uint32_t& lo)
{
    unsigned short ha, la, hb, lb;
    bf16_split(a, ha, la);
    bf16_split(b, hb, lb);
    hi = (uint32_t)ha | ((uint32_t)hb << 16);
    lo = (uint32_t)la | ((uint32_t)lb << 16);
}

// ===================== double-buffered bf16 HMMA GEMM (R8, proven) =========
#define BKS  16
#define NST  (GK / BKS)
#define AST  18

template<int MODE>
__global__ __launch_bounds__(256)
void gemm_mma(const float* __restrict__ Ap, const float* __restrict__ Bp,
              float* __restrict__ Cp, int N)
{
    __shared__ __nv_bfloat16 sA[2][2][128][AST];
    __shared__ __nv_bfloat16 sB[2][2][128][AST];

    const int tid  = threadIdx.x;
    const int wid  = tid >> 5;
    const int lane = tid & 31;
    const int wm   = wid & 1;
    const int wn   = wid >> 1;
    const int gid  = lane >> 2;
    const int tig  = lane & 3;
    const int row0 = blockIdx.y * 128;
    const int col0 = blockIdx.x * 128;

    const float* A = (MODE == 1) ? g_attn : Ap;

    float d[4][4][4];
    #pragma unroll
    for (int i = 0; i < 4; i++)
        #pragma unroll
        for (int j = 0; j < 4; j++)
            #pragma unroll
            for (int e = 0; e < 4; e++) d[i][j][e] = 0.f;

    const int ar0 = tid >> 2, ac0 = (tid & 3) * 4;
    float4 va[2];
    float  vb[2][4];

    #pragma unroll
    for (int i = 0; i < 2; i++)
        va[i] = *(const float4*)(A + (size_t)(row0 + ar0 + i * 64) * GK + ac0);
    #pragma unroll
    for (int jj = 0; jj < 2; jj++)
        #pragma unroll
        for (int c = 0; c < 4; c++)
            vb[jj][c] = Bp[(size_t)(wid + 8 * jj) * N + col0 + lane + 32 * c];

    #pragma unroll
    for (int i = 0; i < 2; i++) {
        const int ra = ar0 + i * 64;
        const float xs[4] = {va[i].x, va[i].y, va[i].z, va[i].w};
        #pragma unroll
        for (int j = 0; j < 2; j++) {
            uint32_t hi, lo;
            split2(xs[2 * j + 0], xs[2 * j + 1], hi, lo);
            *(uint32_t*)&sA[0][0][ra][ac0 + 2 * j] = hi;
            *(uint32_t*)&sA[0][1][ra][ac0 + 2 * j] = lo;
        }
    }
    #pragma unroll
    for (int jj = 0; jj < 2; jj++)
        #pragma unroll
        for (int c = 0; c < 4; c++) {
            unsigned short hh, ll;
            bf16_split(vb[jj][c], hh, ll);
            sB[0][0][lane + 32 * c][wid + 8 * jj] = __ushort_as_bfloat16(hh);
            sB[0][1][lane + 32 * c][wid + 8 * jj] = __ushort_as_bfloat16(ll);
        }
    __syncthreads();

    const int kb = tig * 2;
    for (int kt = 0; kt < NST; kt++) {
        const int buf = kt & 1;
        if (kt + 1 < NST) {
            const int k0 = (kt + 1) * BKS;
            #pragma unroll
            for (int i = 0; i < 2; i++)
                va[i] = *(const float4*)(A + (size_t)(row0 + ar0 + i * 64) * GK + k0 + ac0);
            #pragma unroll
            for (int jj = 0; jj < 2; jj++)
                #pragma unroll
                for (int c = 0; c < 4; c++)
                    vb[jj][c] = Bp[(size_t)(k0 + wid + 8 * jj) * N + col0 + lane + 32 * c];
        }

        uint32_t Ah[4][4], Al[4][4];
        #pragma unroll
        for (int mi = 0; mi < 4; mi++) {
            const int r0 = wm * 64 + mi * 16 + gid;
            Ah[mi][0] = *(const uint32_t*)&sA[buf][0][r0][kb];
            Ah[mi][1] = *(const uint32_t*)&sA[buf][0][r0 + 8][kb];
            Ah[mi][2] = *(const uint32_t*)&sA[buf][0][r0][kb + 8];
            Ah[mi][3] = *(const uint32_t*)&sA[buf][0][r0 + 8][kb + 8];
            Al[mi][0] = *(const uint32_t*)&sA[buf][1][r0][kb];
            Al[mi][1] = *(const uint32_t*)&sA[buf][1][r0 + 8][kb];
            Al[mi][2] = *(const uint32_t*)&sA[buf][1][r0][kb + 8];
            Al[mi][3] = *(const uint32_t*)&sA[buf][1][r0 + 8][kb + 8];
        }
        uint32_t Bh[4][2], Bl[4][2];
        #pragma unroll
        for (int ng = 0; ng < 4; ng++) {
            const int nr = wn * 32 + ng * 8 + gid;
            Bh[ng][0] = *(const uint32_t*)&sB[buf][0][nr][kb];
            Bh[ng][1] = *(const uint32_t*)&sB[buf][0][nr][kb + 8];
            Bl[ng][0] = *(const uint32_t*)&sB[buf][1][nr][kb];
            Bl[ng][1] = *(const uint32_t*)&sB[buf][1][nr][kb + 8];
        }
        #pragma unroll
        for (int mi = 0; mi < 4; mi++)
            #pragma unroll
            for (int ng = 0; ng < 4; ng++) {
                MMA_BF16(d[mi][ng], Ah[mi], Bh[ng][0], Bh[ng][1]);
                MMA_BF16(d[mi][ng], Ah[mi], Bl[ng][0], Bl[ng][1]);
                MMA_BF16(d[mi][ng], Al[mi], Bh[ng][0], Bh[ng][1]);
            }

        if (kt + 1 < NST) {
            const int nb = buf ^ 1;
            #pragma unroll
            for (int i = 0; i < 2; i++) {
                const int ra = ar0 + i * 64;
                const float xs[4] = {va[i].x, va[i].y, va[i].z, va[i].w};
                #pragma unroll
                for (int j = 0; j < 2; j++) {
                    uint32_t hi, lo;
                    split2(xs[2 * j + 0], xs[2 * j + 1], hi, lo);
                    *(uint32_t*)&sA[nb][0][ra][ac0 + 2 * j] = hi;
                    *(uint32_t*)&sA[nb][1][ra][ac0 + 2 * j] = lo;
                }
            }
            #pragma unroll
            for (int jj = 0; jj < 2; jj++)
                #pragma unroll
                for (int c = 0; c < 4; c++) {
                    unsigned short hh, ll;
                    bf16_split(vb[jj][c], hh, ll);
                    sB[nb][0][lane + 32 * c][wid + 8 * jj] = __ushort_as_bfloat16(hh);
                    sB[nb][1][lane + 32 * c][wid + 8 * jj] = __ushort_as_bfloat16(ll);
                }
        }
        __syncthreads();
    }

    // ---------------- epilogue ----------------
    #pragma unroll
    for (int mi = 0; mi < 4; mi++)
        #pragma unroll
        for (int ng = 0; ng < 4; ng++) {
            const int n = col0 + wn * 32 + ng * 8 + tig * 2;
            #pragma unroll
            for (int h = 0; h < 2; h++) {
                const int m = row0 + wm * 64 + mi * 16 + gid + h * 8;
                float2 v;
                v.x = d[mi][ng][h * 2 + 0];
                v.y = d[mi][ng][h * 2 + 1];
                if (MODE == 0) {
                    const int b = m >> 11, t = m & (T_ - 1);
                    const int sidx = n >> 10;
                    const int dmi  = n & (D_MODEL - 1);
                    const int hh = dmi >> 6, dk = dmi & (DKH - 1);
                    const int bh = (b << 4) + hh;
                    if (sidx == 0) {            // Q: pre-scale + split
                        uint32_t hi, lo;
                        split2(0.125f * v.x, 0.125f * v.y, hi, lo);
                        const size_t idx = ((size_t)bh * T_ + t) * DKH + dk;
                        *(uint32_t*)&g_qh[idx] = hi;
                        *(uint32_t*)&g_ql[idx] = lo;
                    } else if (sidx == 1) {     // K: split
                        uint32_t hi, lo;
                        split2(v.x, v.y, hi, lo);
                        const size_t idx = ((size_t)bh * T_ + t) * DKH + dk;
                        *(uint32_t*)&g_kh[idx] = hi;
                        *(uint32_t*)&g_kl[idx] = lo;
                    } else {                    // V: split + transpose to [dk][t]
                        unsigned short h0, l0, h1, l1;
                        bf16_split(v.x, h0, l0);
                        bf16_split(v.y, h1, l1);
                        const size_t i0 = ((size_t)bh * DKH + dk) * T_ + t;
                        g_vh[i0] = __ushort_as_bfloat16(h0);
                        g_vl[i0] = __ushort_as_bfloat16(l0);
                        g_vh[i0 + T_] = __ushort_as_bfloat16(h1);
                        g_vl[i0 + T_] = __ushort_as_bfloat16(l1);
                    }
                } else {
                    *(float2*)(Cp + (size_t)m * N + n) = v;
                }
            }
        }
}

// ===================== bf16 HMMA causal flash attention ====================
// 128 q-rows/CTA, 8 warps x 16 rows, 64-key tiles. Inputs pre-split bf16
// (Q pre-scaled, V pre-transposed). 2 CTAs/SM for load/compute overlap.
#define VST 72

__global__ __launch_bounds__(256, 2)
void attn_mma()
{
    __shared__ __align__(16) __nv_bfloat16 sKh[64][VST], sKl[64][VST];
    __shared__ __align__(16) __nv_bfloat16 sVh[64][VST], sVl[64][VST];

    const int bh  = blockIdx.y;
    const int q0  = blockIdx.x * 128;
    const int tid = threadIdx.x;
    const int wid = tid >> 5;
    const int lane = tid & 31;
    const int gid = lane >> 2;
    const int tig = lane & 3;

    const __nv_bfloat16* Qh_g = g_qh + ((size_t)bh * T_ + q0) * DKH;
    const __nv_bfloat16* Ql_g = g_ql + ((size_t)bh * T_ + q0) * DKH;
    const __nv_bfloat16* Kh_g = g_kh + (size_t)bh * T_ * DKH;
    const __nv_bfloat16* Kl_g = g_kl + (size_t)bh * T_ * DKH;
    const __nv_bfloat16* Vh_g = g_vh + (size_t)bh * DKH * T_;
    const __nv_bfloat16* Vl_g = g_vl + (size_t)bh * DKH * T_;
    const float LOG2E = 1.4426950408889634f;

    // ---- Q fragments (staged through sKh/sKl in two 64-row passes) ----
    uint32_t Qh[4][4], Ql[4][4];
    #pragma unroll
    for (int pass = 0; pass < 2; pass++) {
        #pragma unroll
        for (int i = 0; i < 2; i++) {
            const int c = tid + i * 256;
            const int rr = c >> 3, cc = (c & 7) * 8;
            *(uint4*)&sKh[rr][cc] = *(const uint4*)(Qh_g + (size_t)(pass * 64 + rr) * DKH + cc);
            *(uint4*)&sKl[rr][cc] = *(const uint4*)(Ql_g + (size_t)(pass * 64 + rr) * DKH + cc);
        }
        __syncthreads();
        if ((wid >> 2) == pass) {
            const int rb = (wid & 3) * 16 + gid;
            #pragma unroll
            for (int ks = 0; ks < 4; ks++) {
                const int kb = ks * 16 + tig * 2;
                Qh[ks][0] = *(const uint32_t*)&sKh[rb][kb];
                Qh[ks][1] = *(const uint32_t*)&sKh[rb + 8][kb];
                Qh[ks][2] = *(const uint32_t*)&sKh[rb][kb + 8];
                Qh[ks][3] = *(const uint32_t*)&sKh[rb + 8][kb + 8];
                Ql[ks][0] = *(const uint32_t*)&sKl[rb][kb];
                Ql[ks][1] = *(const uint32_t*)&sKl[rb + 8][kb];
                Ql[ks][2] = *(const uint32_t*)&sKl[rb][kb + 8];
                Ql[ks][3] = *(const uint32_t*)&sKl[rb + 8][kb + 8];
            }
        }
        __syncthreads();
    }

    float O[8][4];
    #pragma unroll
    for (int i = 0; i < 8; i++)
        #pragma unroll
        for (int e = 0; e < 4; e++) O[i][e] = 0.f;
    float mr[2] = {-1e30f, -1e30f}, lr[2] = {0.f, 0.f};

    const int qA = q0 + wid * 16 + gid;
    const int ntiles = (q0 >> 6) + 2;

    for (int t = 0; t < ntiles; t++) {
        const int k0 = t * 64;
        // global loads first (in flight across the barrier)
        uint4 kh[2], kl[2], vh[2], vl[2];
        #pragma unroll
        for (int i = 0; i < 2; i++) {
            const int c = tid + i * 256;
            const int rr = c >> 3, cc = (c & 7) * 8;
            kh[i] = *(const uint4*)(Kh_g + (size_t)(k0 + rr) * DKH + cc);
            kl[i] = *(const uint4*)(Kl_g + (size_t)(k0 + rr) * DKH + cc);
            vh[i] = *(const uint4*)(Vh_g + (size_t)rr * T_ + k0 + cc);   // rr = dk
            vl[i] = *(const uint4*)(Vl_g + (size_t)rr * T_ + k0 + cc);
        }
        __syncthreads();   // prev tile's compute done
        #pragma unroll
        for (int i = 0; i < 2; i++) {
            const int c = tid + i * 256;
            const int rr = c >> 3, cc = (c & 7) * 8;
            *(uint4*)&sKh[rr][cc] = kh[i];
            *(uint4*)&sKl[rr][cc] = kl[i];
            *(uint4*)&sVh[rr][cc] = vh[i];
            *(uint4*)&sVl[rr][cc] = vl[i];
        }
        __syncthreads();

        if (k0 <= q0 + wid * 16 + 15) {
            // ---- S = (Q*scale) @ K^T ----
            float S[8][4];
            #pragma unroll
            for (int i = 0; i < 8; i++)
                #pragma unroll
                for (int e = 0; e < 4; e++) S[i][e] = 0.f;
            #pragma unroll
            for (int ks = 0; ks < 4; ks++) {
                const int kb = ks * 16 + tig * 2;
                #pragma unroll
                for (int ng = 0; ng < 8; ng++) {
                    const int nr = ng * 8 + gid;
                    uint32_t bh0 = *(const uint32_t*)&sKh[nr][kb];
                    uint32_t bh1 = *(const uint32_t*)&sKh[nr][kb + 8];
                    uint32_t bl0 = *(const uint32_t*)&sKl[nr][kb];
                    uint32_t bl1 = *(const uint32_t*)&sKl[nr][kb + 8];
                    MMA_BF16(S[ng], Qh[ks], bh0, bh1);
                    MMA_BF16(S[ng], Qh[ks], bl0, bl1);
                    MMA_BF16(S[ng], Ql[ks], bh0, bh1);
                }
            }
            // ---- causal mask ----
            if (k0 + 63 > q0 + wid * 16) {
                #pragma unroll
                for (int ng = 0; ng < 8; ng++)
                    #pragma unroll
                    for (int e = 0; e < 4; e++) {
                        const int key = k0 + ng * 8 + tig * 2 + (e & 1);
                        const int q   = qA + (e >> 1) * 8;
                        if (key > q) S[ng][e] = -1e30f;
                    }
            }
            // ---- online softmax ----
            #pragma unroll
            for (int h = 0; h < 2; h++) {
                float mt = -1e30f;
                #pragma unroll
                for (int ng = 0; ng < 8; ng++)
                    mt = fmaxf(mt, fmaxf(S[ng][2 * h], S[ng][2 * h + 1]));
                mt = fmaxf(mt, __shfl_xor_sync(0xffffffff, mt, 1));
                mt = fmaxf(mt, __shfl_xor_sync(0xffffffff, mt, 2));
                const float mn = fmaxf(mr[h], mt);
                const float alpha = exp2f((mr[h] - mn) * LOG2E);
                float rs = 0.f;
                #pragma unroll
                for (int ng = 0; ng < 8; ng++) {
                    float p0 = exp2f((S[ng][2 * h] - mn) * LOG2E);
                    float p1 = exp2f((S[ng][2 * h + 1] - mn) * LOG2E);
                    S[ng][2 * h] = p0;
                    S[ng][2 * h + 1] = p1;
                    rs += p0 + p1;
                }
                rs += __shfl_xor_sync(0xffffffff, rs, 1);
                rs += __shfl_xor_sync(0xffffffff, rs, 2);
                lr[h] = lr[h] * alpha + rs;
                mr[h] = mn;
                #pragma unroll
                for (int ng = 0; ng < 8; ng++) {
                    O[ng][2 * h] *= alpha;
                    O[ng][2 * h + 1] *= alpha;
                }
            }
            // ---- O += P @ V ----
            #pragma unroll
            for (int ks = 0; ks < 4; ks++) {
                uint32_t Ph[4], Pl[4];
                split2(S[2 * ks][0],     S[2 * ks][1],     Ph[0], Pl[0]);
                split2(S[2 * ks][2],     S[2 * ks][3],     Ph[1], Pl[1]);
                split2(S[2 * ks + 1][0], S[2 * ks + 1][1], Ph[2], Pl[2]);
                split2(S[2 * ks + 1][2], S[2 * ks + 1][3], Ph[3], Pl[3]);
                const int kb = ks * 16 + tig * 2;
                #pragma unroll
                for (int ng = 0; ng < 8; ng++) {
                    const int nr = ng * 8 + gid;
                    uint32_t vh0 = *(const uint32_t*)&sVh[nr][kb];
                    uint32_t vh1 = *(const uint32_t*)&sVh[nr][kb + 8];
                    uint32_t vl0 = *(const uint32_t*)&sVl[nr][kb];
                    uint32_t vl1 = *(const uint32_t*)&sVl[nr][kb + 8];
                    MMA_BF16(O[ng], Ph, vh0, vh1);
                    MMA_BF16(O[ng], Ph, vl0, vl1);
                    MMA_BF16(O[ng], Pl, vh0, vh1);
                }
            }
        }
    }

    // ---- epilogue: normalize + write (B,T,D) ----
    const int b = bh >> 4, h = bh & 15;
    #pragma unroll
    for (int hh = 0; hh < 2; hh++) {
        const float inv = 1.f / lr[hh];
        const int q = qA + hh * 8;
        float* og = g_attn + ((size_t)(b * T_ + q)) * D_MODEL + h * DKH;
        #pragma unroll
        for (int ng = 0; ng < 8; ng++) {
            float2 v;
            v.x = O[ng][2 * hh] * inv;
            v.y = O[ng][2 * hh + 1] * inv;
            *(float2*)(og + ng * 8 + tig * 2) = v;
        }
    }
}

// ---------------------------------------------------------------------------
extern "C" void kernel_launch(void* const* d_in, const int* in_sizes, int n_in,
                              void* d_out, int out_size)
{
    const float* x     = (const float*)d_in[0];
    const float* w_qkv = (const float*)d_in[1];
    const float* w_out = (const float*)d_in[2];
    float* out = (float*)d_out;

    gemm_mma<0><<<dim3(N_QKV / 128, M_TOT / 128), 256>>>(x, w_qkv, nullptr, N_QKV);
    attn_mma<<<dim3(T_ / 128, B_ * N_HEADS), 256>>>();
    gemm_mma<1><<<dim3(D_MODEL / 128, M_TOT / 128), 256>>>(nullptr, w_out, out, D_MODEL);
}